// round 1
// baseline (speedup 1.0000x reference)
#include <cuda_runtime.h>
#include <cuda_bf16.h>

// Problem constants
#define TT 2048
#define EE 1024
#define DD 1024
#define HH 16
#define HDIM 64
#define BB 2

// Scratch (no runtime allocation allowed)
__device__ float g_qkv[(size_t)BB * TT * 3 * DD];  // [4096, 3072]
__device__ float g_y[(size_t)BB * TT * DD];        // [4096, 1024]

// ---------------------------------------------------------------------------
// SGEMM: C[M,N] = A[M,K] @ B[K,N] + bias[N]
// 128x128 block tile, BK=8, 256 threads, 8x8 micro-tile per thread.
// ---------------------------------------------------------------------------
__global__ __launch_bounds__(256) void sgemm_bias_kernel(
    const float* __restrict__ A, const float* __restrict__ Bm,
    const float* __restrict__ bias, float* __restrict__ C,
    int M, int N, int K)
{
    __shared__ float As[8][128];   // k-major
    __shared__ float Bs[8][128];

    const int tid = threadIdx.x;
    const int tx = tid & 15, ty = tid >> 4;
    const int m0 = blockIdx.y * 128, n0 = blockIdx.x * 128;

    const int aRow = tid >> 1;
    const int a4   = (tid & 1) * 4;
    const int bRow = tid >> 5;
    const int b4   = (tid & 31) * 4;

    float acc[8][8];
    #pragma unroll
    for (int i = 0; i < 8; i++)
        #pragma unroll
        for (int j = 0; j < 8; j++) acc[i][j] = 0.f;

    for (int k0 = 0; k0 < K; k0 += 8) {
        // prefetch into registers (overlaps previous tile's compute)
        float4 av = *(const float4*)&A[(size_t)(m0 + aRow) * K + k0 + a4];
        float4 bv = *(const float4*)&Bm[(size_t)(k0 + bRow) * N + n0 + b4];
        __syncthreads();
        As[a4 + 0][aRow] = av.x;
        As[a4 + 1][aRow] = av.y;
        As[a4 + 2][aRow] = av.z;
        As[a4 + 3][aRow] = av.w;
        *(float4*)&Bs[bRow][b4] = bv;
        __syncthreads();

        #pragma unroll
        for (int kk = 0; kk < 8; kk++) {
            float4 a0 = *(const float4*)&As[kk][ty * 8];
            float4 a1 = *(const float4*)&As[kk][ty * 8 + 4];
            float4 b0 = *(const float4*)&Bs[kk][tx * 8];
            float4 b1 = *(const float4*)&Bs[kk][tx * 8 + 4];
            float ar[8] = {a0.x, a0.y, a0.z, a0.w, a1.x, a1.y, a1.z, a1.w};
            float br[8] = {b0.x, b0.y, b0.z, b0.w, b1.x, b1.y, b1.z, b1.w};
            #pragma unroll
            for (int i = 0; i < 8; i++)
                #pragma unroll
                for (int j = 0; j < 8; j++)
                    acc[i][j] += ar[i] * br[j];
        }
    }

    float bsv[8];
    #pragma unroll
    for (int j = 0; j < 8; j++) bsv[j] = bias[n0 + tx * 8 + j];

    #pragma unroll
    for (int i = 0; i < 8; i++) {
        size_t row = (size_t)(m0 + ty * 8 + i) * N + n0 + tx * 8;
        float4 o0 = make_float4(acc[i][0] + bsv[0], acc[i][1] + bsv[1],
                                acc[i][2] + bsv[2], acc[i][3] + bsv[3]);
        float4 o1 = make_float4(acc[i][4] + bsv[4], acc[i][5] + bsv[5],
                                acc[i][6] + bsv[6], acc[i][7] + bsv[7]);
        *(float4*)&C[row]     = o0;
        *(float4*)&C[row + 4] = o1;
    }
}

// ---------------------------------------------------------------------------
// Flash attention (fp32, causal). One CTA handles a 64-query tile of one
// (b, h). 256 threads as 16x16 grid; each thread owns a 4x4 S / 4x4 O
// micro-tile. Q and K stored d-major in smem for aligned LDS.128 fragments.
// P transposed into Pt[c][r] (pad 65) so O-GEMM also streams with LDS.128.
// ---------------------------------------------------------------------------
__global__ __launch_bounds__(256) void flash_attn_kernel(
    const float* __restrict__ qkv, float* __restrict__ y)
{
    extern __shared__ float sm[];
    float* Qt = sm;             // [64][64]  Qt[d][r]
    float* Kt = sm + 4096;      // [64][64]  Kt[d][c]
    float* Vs = sm + 8192;      // [64][64]  Vs[c][d]
    float* Pt = sm + 12288;     // [64][65]  Pt[c][r]

    const int qt = blockIdx.x;          // query tile 0..31
    const int bh = blockIdx.y;          // b*H + h
    const int b = bh >> 4, h = bh & 15;
    const int tid = threadIdx.x;
    const int tx = tid & 15, ty = tid >> 4;
    const int q0 = qt * 64;
    const size_t base = ((size_t)b * TT) * 3072 + (size_t)h * 64;
    const float scale = 0.125f;         // 1/sqrt(64)

    // Load Q tile transposed (d-major), pre-scaled.
    #pragma unroll
    for (int it = 0; it < 4; it++) {
        int idx = tid + 256 * it;
        int r = idx & 63, d4 = idx >> 6;
        float4 v = *(const float4*)&qkv[base + (size_t)(q0 + r) * 3072 + d4 * 4];
        Qt[(d4 * 4 + 0) * 64 + r] = v.x * scale;
        Qt[(d4 * 4 + 1) * 64 + r] = v.y * scale;
        Qt[(d4 * 4 + 2) * 64 + r] = v.z * scale;
        Qt[(d4 * 4 + 3) * 64 + r] = v.w * scale;
    }

    float m_i[4], l_i[4], O[4][4];
    #pragma unroll
    for (int i = 0; i < 4; i++) {
        m_i[i] = -1e30f;
        l_i[i] = 0.f;
        #pragma unroll
        for (int j = 0; j < 4; j++) O[i][j] = 0.f;
    }
    __syncthreads();

    for (int kt = 0; kt <= qt; kt++) {
        // Load K tile (transposed, d-major) and V tile (row-major).
        #pragma unroll
        for (int it = 0; it < 4; it++) {
            int idx = tid + 256 * it;
            int c = idx & 63, d4 = idx >> 6;
            float4 v = *(const float4*)&qkv[base + 1024 +
                                            (size_t)(kt * 64 + c) * 3072 + d4 * 4];
            Kt[(d4 * 4 + 0) * 64 + c] = v.x;
            Kt[(d4 * 4 + 1) * 64 + c] = v.y;
            Kt[(d4 * 4 + 2) * 64 + c] = v.z;
            Kt[(d4 * 4 + 3) * 64 + c] = v.w;
            int c2 = idx >> 4, e4 = idx & 15;
            float4 w = *(const float4*)&qkv[base + 2048 +
                                            (size_t)(kt * 64 + c2) * 3072 + e4 * 4];
            *(float4*)&Vs[c2 * 64 + e4 * 4] = w;
        }
        __syncthreads();

        // S = (Q*scale) @ K^T  (64x64), 4x4 per thread.
        float s[4][4];
        #pragma unroll
        for (int i = 0; i < 4; i++)
            #pragma unroll
            for (int j = 0; j < 4; j++) s[i][j] = 0.f;

        #pragma unroll 4
        for (int kk = 0; kk < 64; kk++) {
            float4 qv = *(const float4*)&Qt[kk * 64 + ty * 4];
            float4 kv = *(const float4*)&Kt[kk * 64 + tx * 4];
            float qa[4] = {qv.x, qv.y, qv.z, qv.w};
            float ka[4] = {kv.x, kv.y, kv.z, kv.w};
            #pragma unroll
            for (int i = 0; i < 4; i++)
                #pragma unroll
                for (int j = 0; j < 4; j++)
                    s[i][j] += qa[i] * ka[j];
        }

        // Causal mask on the diagonal tile only.
        if (kt == qt) {
            #pragma unroll
            for (int i = 0; i < 4; i++) {
                int r = ty * 4 + i;
                #pragma unroll
                for (int j = 0; j < 4; j++)
                    if (tx * 4 + j > r) s[i][j] = -1e30f;
            }
        }

        // Online softmax (per-row reductions across the 16 tx lanes).
        #pragma unroll
        for (int i = 0; i < 4; i++) {
            float rm = s[i][0];
            #pragma unroll
            for (int j = 1; j < 4; j++) rm = fmaxf(rm, s[i][j]);
            #pragma unroll
            for (int off = 8; off >= 1; off >>= 1)
                rm = fmaxf(rm, __shfl_xor_sync(0xffffffffu, rm, off));
            float nm = fmaxf(m_i[i], rm);
            float alpha = __expf(m_i[i] - nm);
            m_i[i] = nm;
            float ls = 0.f;
            #pragma unroll
            for (int j = 0; j < 4; j++) {
                float p = __expf(s[i][j] - nm);
                s[i][j] = p;
                ls += p;
            }
            #pragma unroll
            for (int off = 8; off >= 1; off >>= 1)
                ls += __shfl_xor_sync(0xffffffffu, ls, off);
            l_i[i] = l_i[i] * alpha + ls;
            #pragma unroll
            for (int j = 0; j < 4; j++) O[i][j] *= alpha;
        }

        // Stage P transposed: Pt[c][r].
        #pragma unroll
        for (int i = 0; i < 4; i++)
            #pragma unroll
            for (int j = 0; j < 4; j++)
                Pt[(tx * 4 + j) * 65 + ty * 4 + i] = s[i][j];
        __syncthreads();

        // O[r][d] += sum_c P[r][c] * V[c][d]
        #pragma unroll 4
        for (int c = 0; c < 64; c++) {
            float4 vv = *(const float4*)&Vs[c * 64 + tx * 4];
            float va[4] = {vv.x, vv.y, vv.z, vv.w};
            float pr[4];
            #pragma unroll
            for (int i = 0; i < 4; i++) pr[i] = Pt[c * 65 + ty * 4 + i];
            #pragma unroll
            for (int i = 0; i < 4; i++)
                #pragma unroll
                for (int j = 0; j < 4; j++)
                    O[i][j] += pr[i] * va[j];
        }
        __syncthreads();
    }

    // Normalize and write y[b, t, h*64 + d]  (layout [B*T, 1024]).
    #pragma unroll
    for (int i = 0; i < 4; i++) {
        float inv = 1.0f / l_i[i];
        size_t off = ((size_t)b * TT + q0 + ty * 4 + i) * 1024 + h * 64 + tx * 4;
        float4 o = make_float4(O[i][0] * inv, O[i][1] * inv,
                               O[i][2] * inv, O[i][3] * inv);
        *(float4*)&y[off] = o;
    }
}

// ---------------------------------------------------------------------------
extern "C" void kernel_launch(void* const* d_in, const int* in_sizes, int n_in,
                              void* d_out, int out_size)
{
    const float* x      = (const float*)d_in[0];
    const float* W_attn = (const float*)d_in[1];
    const float* b_attn = (const float*)d_in[2];
    const float* W_proj = (const float*)d_in[3];
    const float* b_proj = (const float*)d_in[4];
    float* out = (float*)d_out;

    float* qkv = nullptr;
    float* y   = nullptr;
    cudaGetSymbolAddress((void**)&qkv, g_qkv);
    cudaGetSymbolAddress((void**)&y, g_y);

    const int M = BB * TT;  // 4096

    // Stage 1: QKV = x @ W_attn + b_attn   [4096, 3072]
    {
        dim3 grid(3 * DD / 128, M / 128);  // (24, 32)
        sgemm_bias_kernel<<<grid, 256>>>(x, W_attn, b_attn, qkv, M, 3 * DD, EE);
    }

    // Stage 2: flash attention -> y [4096, 1024]
    {
        int smem_bytes = (3 * 64 * 64 + 64 * 65) * (int)sizeof(float);  // 65792
        static bool attr_set = false;
        if (!attr_set) {
            cudaFuncSetAttribute(flash_attn_kernel,
                                 cudaFuncAttributeMaxDynamicSharedMemorySize,
                                 smem_bytes);
            attr_set = true;
        }
        dim3 grid(TT / 64, BB * HH);  // (32, 32)
        flash_attn_kernel<<<grid, 256, smem_bytes>>>(qkv, y);
    }

    // Stage 3: out = y @ W_proj + b_proj   [4096, 1024]
    {
        dim3 grid(EE / 128, M / 128);  // (8, 32)
        sgemm_bias_kernel<<<grid, 256>>>(y, W_proj, b_proj, out, M, EE, DD);
    }
}

// round 6
// speedup vs baseline: 1.4193x; 1.4193x over previous
#include <cuda_runtime.h>
#include <cuda_bf16.h>
#include <cstdint>

// Problem constants
#define TT 2048
#define EE 1024
#define DD 1024
#define HH 16
#define HDIM 64
#define BB 2
#define MM (BB * TT)   // 4096
#define GK 1024        // K of both GEMMs

// ---------------------------------------------------------------------------
// Scratch (no runtime allocation allowed)
// ---------------------------------------------------------------------------
__device__ float g_qkv[(size_t)MM * 3 * DD];          // [4096, 3072] fp32
__device__ float g_y[(size_t)MM * DD];                // [4096, 1024] fp32
__device__ __nv_bfloat16 g_xh[(size_t)MM * EE];
__device__ __nv_bfloat16 g_xl[(size_t)MM * EE];
__device__ __nv_bfloat16 g_wah[(size_t)3 * DD * EE];  // W_attn^T [3072,1024]
__device__ __nv_bfloat16 g_wal[(size_t)3 * DD * EE];
__device__ __nv_bfloat16 g_wph[(size_t)EE * DD];      // W_proj^T [1024,1024]
__device__ __nv_bfloat16 g_wpl[(size_t)EE * DD];
__device__ __nv_bfloat16 g_yh[(size_t)MM * DD];
__device__ __nv_bfloat16 g_yl[(size_t)MM * DD];

// ---------------------------------------------------------------------------
// Warp-MMA helpers (base-target PTX only: ldmatrix sm_75+, bf16 mma sm_80+)
// ---------------------------------------------------------------------------
__device__ __forceinline__ uint32_t smem_u32(const void* p) {
    uint32_t a;
    asm("{ .reg .u64 t; cvta.to.shared.u64 t, %1; cvt.u32.u64 %0, t; }"
        : "=r"(a) : "l"(p));
    return a;
}

#define LDSM_X4(R, addr) \
    asm volatile("ldmatrix.sync.aligned.m8n8.x4.shared.b16 {%0,%1,%2,%3}, [%4];" \
        : "=r"((R)[0]), "=r"((R)[1]), "=r"((R)[2]), "=r"((R)[3]) : "r"(addr))

#define MMA_BF16(D, A, B) \
    asm volatile("mma.sync.aligned.m16n8k16.row.col.f32.bf16.bf16.f32 " \
        "{%0,%1,%2,%3},{%4,%5,%6,%7},{%8,%9},{%0,%1,%2,%3};" \
        : "+f"((D)[0]), "+f"((D)[1]), "+f"((D)[2]), "+f"((D)[3]) \
        : "r"((A)[0]), "r"((A)[1]), "r"((A)[2]), "r"((A)[3]), \
          "r"((B)[0]), "r"((B)[1]))

// ---------------------------------------------------------------------------
// Split/convert kernels
// ---------------------------------------------------------------------------
__global__ void split_kernel(const float* __restrict__ in,
                             __nv_bfloat16* __restrict__ hi,
                             __nv_bfloat16* __restrict__ lo, int n4)
{
    int i = blockIdx.x * blockDim.x + threadIdx.x;
    if (i >= n4) return;
    float4 v = ((const float4*)in)[i];
    __nv_bfloat16 h0 = __float2bfloat16(v.x);
    __nv_bfloat16 h1 = __float2bfloat16(v.y);
    __nv_bfloat16 h2 = __float2bfloat16(v.z);
    __nv_bfloat16 h3 = __float2bfloat16(v.w);
    __nv_bfloat16 l0 = __float2bfloat16(v.x - __bfloat162float(h0));
    __nv_bfloat16 l1 = __float2bfloat16(v.y - __bfloat162float(h1));
    __nv_bfloat16 l2 = __float2bfloat16(v.z - __bfloat162float(h2));
    __nv_bfloat16 l3 = __float2bfloat16(v.w - __bfloat162float(h3));
    ((__nv_bfloat162*)hi)[2*i]   = __nv_bfloat162(h0, h1);
    ((__nv_bfloat162*)hi)[2*i+1] = __nv_bfloat162(h2, h3);
    ((__nv_bfloat162*)lo)[2*i]   = __nv_bfloat162(l0, l1);
    ((__nv_bfloat162*)lo)[2*i+1] = __nv_bfloat162(l2, l3);
}

// W [K,N] fp32 -> T [N,K] bf16 hi/lo
__global__ void transpose_split_kernel(const float* __restrict__ W,
                                       __nv_bfloat16* __restrict__ Th,
                                       __nv_bfloat16* __restrict__ Tl,
                                       int K, int N)
{
    __shared__ float tile[32][33];
    int kb = blockIdx.y * 32, nb = blockIdx.x * 32;
    int x = threadIdx.x, y0 = threadIdx.y;  // 32 x 8
    #pragma unroll
    for (int dy = 0; dy < 32; dy += 8)
        tile[y0 + dy][x] = W[(size_t)(kb + y0 + dy) * N + nb + x];
    __syncthreads();
    #pragma unroll
    for (int dy = 0; dy < 32; dy += 8) {
        float v = tile[x][y0 + dy];
        __nv_bfloat16 h = __float2bfloat16(v);
        __nv_bfloat16 l = __float2bfloat16(v - __bfloat162float(h));
        size_t o = (size_t)(nb + y0 + dy) * K + kb + x;
        Th[o] = h;
        Tl[o] = l;
    }
}

// ---------------------------------------------------------------------------
// mma.sync split-bf16 GEMM: C[M,N] = A[M,K] @ Bt[N,K]^T + bias[N]
// A/B as hi+lo bf16; computes hh + hl + lh into fp32 accumulators.
// 128x128 block, BK=32, 256 threads (4x2 warps of 32x64 tiles each).
// ---------------------------------------------------------------------------
#define GS 40   // smem row stride in bf16 (conflict-free ldmatrix: 20r mod 32)

__global__ __launch_bounds__(256) void gemm_mma_kernel(
    const __nv_bfloat16* __restrict__ Ah, const __nv_bfloat16* __restrict__ Al,
    const __nv_bfloat16* __restrict__ Bh, const __nv_bfloat16* __restrict__ Bl,
    const float* __restrict__ bias, float* __restrict__ C,
    int M, int N, int K)
{
    __shared__ __nv_bfloat16 sA[2][128][GS];  // [hi/lo][row][k]
    __shared__ __nv_bfloat16 sB[2][128][GS];  // [hi/lo][n-row][k]

    const int tid = threadIdx.x;
    const int lane = tid & 31;
    const int wid = tid >> 5;
    const int wm = wid & 3;        // 0..3  (32-row slab)
    const int wn = wid >> 2;       // 0..1  (64-col slab)
    const int m0 = blockIdx.y * 128;
    const int n0 = blockIdx.x * 128;

    // gmem loader mapping: 2 threads per 128-row; each loads 16 bf16 (2 uint4)
    const int lrow = tid >> 1;
    const int lseg = (tid & 1) * 16;

    float acc[2][8][4];
    #pragma unroll
    for (int i = 0; i < 2; i++)
        #pragma unroll
        for (int j = 0; j < 8; j++)
            #pragma unroll
            for (int r = 0; r < 4; r++) acc[i][j][r] = 0.f;

    const uint32_t sA0 = smem_u32(&sA[0][0][0]);
    const uint32_t sA1 = smem_u32(&sA[1][0][0]);
    const uint32_t sB0 = smem_u32(&sB[0][0][0]);
    const uint32_t sB1 = smem_u32(&sB[1][0][0]);

    // prefetch chunk 0
    uint4 pre[8];
    {
        size_t ra = (size_t)(m0 + lrow) * K + lseg;
        size_t rb = (size_t)(n0 + lrow) * K + lseg;
        pre[0] = *(const uint4*)&Ah[ra];
        pre[1] = *(const uint4*)&Ah[ra + 8];
        pre[2] = *(const uint4*)&Al[ra];
        pre[3] = *(const uint4*)&Al[ra + 8];
        pre[4] = *(const uint4*)&Bh[rb];
        pre[5] = *(const uint4*)&Bh[rb + 8];
        pre[6] = *(const uint4*)&Bl[rb];
        pre[7] = *(const uint4*)&Bl[rb + 8];
    }

    const int NC = K >> 5;  // 32 chunks
    for (int ch = 0; ch < NC; ch++) {
        // stage to smem
        *(uint4*)&sA[0][lrow][lseg]     = pre[0];
        *(uint4*)&sA[0][lrow][lseg + 8] = pre[1];
        *(uint4*)&sA[1][lrow][lseg]     = pre[2];
        *(uint4*)&sA[1][lrow][lseg + 8] = pre[3];
        *(uint4*)&sB[0][lrow][lseg]     = pre[4];
        *(uint4*)&sB[0][lrow][lseg + 8] = pre[5];
        *(uint4*)&sB[1][lrow][lseg]     = pre[6];
        *(uint4*)&sB[1][lrow][lseg + 8] = pre[7];
        __syncthreads();

        if (ch + 1 < NC) {
            int k0 = (ch + 1) * 32;
            size_t ra = (size_t)(m0 + lrow) * K + k0 + lseg;
            size_t rb = (size_t)(n0 + lrow) * K + k0 + lseg;
            pre[0] = *(const uint4*)&Ah[ra];
            pre[1] = *(const uint4*)&Ah[ra + 8];
            pre[2] = *(const uint4*)&Al[ra];
            pre[3] = *(const uint4*)&Al[ra + 8];
            pre[4] = *(const uint4*)&Bh[rb];
            pre[5] = *(const uint4*)&Bh[rb + 8];
            pre[6] = *(const uint4*)&Bl[rb];
            pre[7] = *(const uint4*)&Bl[rb + 8];
        }

        #pragma unroll
        for (int ks = 0; ks < 2; ks++) {
            // A fragments: [hi/lo][mtile][4]
            uint32_t aA[2][2][4];
            {
                int r = lane & 15, kh = lane >> 4;
                #pragma unroll
                for (int mt = 0; mt < 2; mt++) {
                    uint32_t off =
                        (uint32_t)((wm * 32 + mt * 16 + r) * GS + ks * 16 + kh * 8) * 2;
                    LDSM_X4(aA[0][mt], sA0 + off);
                    LDSM_X4(aA[1][mt], sA1 + off);
                }
            }
            // B fragments: [hi/lo][ntile][2] via x4 over ntile pairs
            uint32_t bB[2][8][2];
            {
                int nr = ((lane >> 4) << 3) + (lane & 7);
                int kc = ks * 16 + (((lane >> 3) & 1) << 3);
                #pragma unroll
                for (int p = 0; p < 4; p++) {
                    uint32_t off =
                        (uint32_t)((wn * 64 + p * 16 + nr) * GS + kc) * 2;
                    uint32_t t[4];
                    LDSM_X4(t, sB0 + off);
                    bB[0][2 * p][0] = t[0]; bB[0][2 * p][1] = t[1];
                    bB[0][2 * p + 1][0] = t[2]; bB[0][2 * p + 1][1] = t[3];
                    LDSM_X4(t, sB1 + off);
                    bB[1][2 * p][0] = t[0]; bB[1][2 * p][1] = t[1];
                    bB[1][2 * p + 1][0] = t[2]; bB[1][2 * p + 1][1] = t[3];
                }
            }
            // hh + hl + lh
            #pragma unroll
            for (int mt = 0; mt < 2; mt++)
                #pragma unroll
                for (int nt = 0; nt < 8; nt++) {
                    MMA_BF16(acc[mt][nt], aA[0][mt], bB[0][nt]);
                    MMA_BF16(acc[mt][nt], aA[0][mt], bB[1][nt]);
                    MMA_BF16(acc[mt][nt], aA[1][mt], bB[0][nt]);
                }
        }
        __syncthreads();
    }

    // Epilogue: fragment -> gmem with bias.
    #pragma unroll
    for (int mt = 0; mt < 2; mt++) {
        int m = m0 + wm * 32 + mt * 16 + (lane >> 2);
        #pragma unroll
        for (int nt = 0; nt < 8; nt++) {
            int n = n0 + wn * 64 + nt * 8 + ((lane & 3) << 1);
            float b0 = bias[n], b1 = bias[n + 1];
            float2 lo = make_float2(acc[mt][nt][0] + b0, acc[mt][nt][1] + b1);
            float2 hi = make_float2(acc[mt][nt][2] + b0, acc[mt][nt][3] + b1);
            *(float2*)&C[(size_t)m * N + n] = lo;
            *(float2*)&C[(size_t)(m + 8) * N + n] = hi;
        }
    }
}

// ---------------------------------------------------------------------------
// Flash attention (fp32, causal) — unchanged known-good R1 kernel.
// ---------------------------------------------------------------------------
__global__ __launch_bounds__(256) void flash_attn_kernel(
    const float* __restrict__ qkv, float* __restrict__ y)
{
    extern __shared__ float sm[];
    float* Qt = sm;             // [64][64]  Qt[d][r]
    float* Kt = sm + 4096;      // [64][64]  Kt[d][c]
    float* Vs = sm + 8192;      // [64][64]  Vs[c][d]
    float* Pt = sm + 12288;     // [64][65]  Pt[c][r]

    const int qt = blockIdx.x;
    const int bh = blockIdx.y;
    const int b = bh >> 4, h = bh & 15;
    const int tid = threadIdx.x;
    const int tx = tid & 15, ty = tid >> 4;
    const int q0 = qt * 64;
    const size_t base = ((size_t)b * TT) * 3072 + (size_t)h * 64;
    const float scale = 0.125f;

    #pragma unroll
    for (int it = 0; it < 4; it++) {
        int idx = tid + 256 * it;
        int r = idx & 63, d4 = idx >> 6;
        float4 v = *(const float4*)&qkv[base + (size_t)(q0 + r) * 3072 + d4 * 4];
        Qt[(d4 * 4 + 0) * 64 + r] = v.x * scale;
        Qt[(d4 * 4 + 1) * 64 + r] = v.y * scale;
        Qt[(d4 * 4 + 2) * 64 + r] = v.z * scale;
        Qt[(d4 * 4 + 3) * 64 + r] = v.w * scale;
    }

    float m_i[4], l_i[4], O[4][4];
    #pragma unroll
    for (int i = 0; i < 4; i++) {
        m_i[i] = -1e30f;
        l_i[i] = 0.f;
        #pragma unroll
        for (int j = 0; j < 4; j++) O[i][j] = 0.f;
    }
    __syncthreads();

    for (int kt = 0; kt <= qt; kt++) {
        #pragma unroll
        for (int it = 0; it < 4; it++) {
            int idx = tid + 256 * it;
            int c = idx & 63, d4 = idx >> 6;
            float4 v = *(const float4*)&qkv[base + 1024 +
                                            (size_t)(kt * 64 + c) * 3072 + d4 * 4];
            Kt[(d4 * 4 + 0) * 64 + c] = v.x;
            Kt[(d4 * 4 + 1) * 64 + c] = v.y;
            Kt[(d4 * 4 + 2) * 64 + c] = v.z;
            Kt[(d4 * 4 + 3) * 64 + c] = v.w;
            int c2 = idx >> 4, e4 = idx & 15;
            float4 w = *(const float4*)&qkv[base + 2048 +
                                            (size_t)(kt * 64 + c2) * 3072 + e4 * 4];
            *(float4*)&Vs[c2 * 64 + e4 * 4] = w;
        }
        __syncthreads();

        float s[4][4];
        #pragma unroll
        for (int i = 0; i < 4; i++)
            #pragma unroll
            for (int j = 0; j < 4; j++) s[i][j] = 0.f;

        #pragma unroll 4
        for (int kk = 0; kk < 64; kk++) {
            float4 qv = *(const float4*)&Qt[kk * 64 + ty * 4];
            float4 kv = *(const float4*)&Kt[kk * 64 + tx * 4];
            float qa[4] = {qv.x, qv.y, qv.z, qv.w};
            float ka[4] = {kv.x, kv.y, kv.z, kv.w};
            #pragma unroll
            for (int i = 0; i < 4; i++)
                #pragma unroll
                for (int j = 0; j < 4; j++)
                    s[i][j] += qa[i] * ka[j];
        }

        if (kt == qt) {
            #pragma unroll
            for (int i = 0; i < 4; i++) {
                int r = ty * 4 + i;
                #pragma unroll
                for (int j = 0; j < 4; j++)
                    if (tx * 4 + j > r) s[i][j] = -1e30f;
            }
        }

        #pragma unroll
        for (int i = 0; i < 4; i++) {
            float rm = s[i][0];
            #pragma unroll
            for (int j = 1; j < 4; j++) rm = fmaxf(rm, s[i][j]);
            #pragma unroll
            for (int off = 8; off >= 1; off >>= 1)
                rm = fmaxf(rm, __shfl_xor_sync(0xffffffffu, rm, off));
            float nm = fmaxf(m_i[i], rm);
            float alpha = __expf(m_i[i] - nm);
            m_i[i] = nm;
            float ls = 0.f;
            #pragma unroll
            for (int j = 0; j < 4; j++) {
                float p = __expf(s[i][j] - nm);
                s[i][j] = p;
                ls += p;
            }
            #pragma unroll
            for (int off = 8; off >= 1; off >>= 1)
                ls += __shfl_xor_sync(0xffffffffu, ls, off);
            l_i[i] = l_i[i] * alpha + ls;
            #pragma unroll
            for (int j = 0; j < 4; j++) O[i][j] *= alpha;
        }

        #pragma unroll
        for (int i = 0; i < 4; i++)
            #pragma unroll
            for (int j = 0; j < 4; j++)
                Pt[(tx * 4 + j) * 65 + ty * 4 + i] = s[i][j];
        __syncthreads();

        #pragma unroll 4
        for (int c = 0; c < 64; c++) {
            float4 vv = *(const float4*)&Vs[c * 64 + tx * 4];
            float va[4] = {vv.x, vv.y, vv.z, vv.w};
            float pr[4];
            #pragma unroll
            for (int i = 0; i < 4; i++) pr[i] = Pt[c * 65 + ty * 4 + i];
            #pragma unroll
            for (int i = 0; i < 4; i++)
                #pragma unroll
                for (int j = 0; j < 4; j++)
                    O[i][j] += pr[i] * va[j];
        }
        __syncthreads();
    }

    #pragma unroll
    for (int i = 0; i < 4; i++) {
        float inv = 1.0f / l_i[i];
        size_t off = ((size_t)b * TT + q0 + ty * 4 + i) * 1024 + h * 64 + tx * 4;
        float4 o = make_float4(O[i][0] * inv, O[i][1] * inv,
                               O[i][2] * inv, O[i][3] * inv);
        *(float4*)&y[off] = o;
    }
}

// ---------------------------------------------------------------------------
extern "C" void kernel_launch(void* const* d_in, const int* in_sizes, int n_in,
                              void* d_out, int out_size)
{
    const float* x      = (const float*)d_in[0];
    const float* W_attn = (const float*)d_in[1];
    const float* b_attn = (const float*)d_in[2];
    const float* W_proj = (const float*)d_in[3];
    const float* b_proj = (const float*)d_in[4];
    float* out = (float*)d_out;

    float *qkv, *y;
    __nv_bfloat16 *xh, *xl, *wah, *wal, *wph, *wpl, *yh, *yl;
    cudaGetSymbolAddress((void**)&qkv, g_qkv);
    cudaGetSymbolAddress((void**)&y, g_y);
    cudaGetSymbolAddress((void**)&xh, g_xh);
    cudaGetSymbolAddress((void**)&xl, g_xl);
    cudaGetSymbolAddress((void**)&wah, g_wah);
    cudaGetSymbolAddress((void**)&wal, g_wal);
    cudaGetSymbolAddress((void**)&wph, g_wph);
    cudaGetSymbolAddress((void**)&wpl, g_wpl);
    cudaGetSymbolAddress((void**)&yh, g_yh);
    cudaGetSymbolAddress((void**)&yl, g_yl);

    int attn_smem = (3 * 64 * 64 + 64 * 65) * (int)sizeof(float);
    static bool attr_set = false;
    if (!attr_set) {
        cudaFuncSetAttribute(flash_attn_kernel,
                             cudaFuncAttributeMaxDynamicSharedMemorySize,
                             attn_smem);
        attr_set = true;
    }

    // 1) splits / transposes
    split_kernel<<<(MM * EE / 4 + 255) / 256, 256>>>(x, xh, xl, MM * EE / 4);
    {
        dim3 g(3 * DD / 32, EE / 32), b(32, 8);
        transpose_split_kernel<<<g, b>>>(W_attn, wah, wal, EE, 3 * DD);
    }
    {
        dim3 g(EE / 32, DD / 32), b(32, 8);
        transpose_split_kernel<<<g, b>>>(W_proj, wph, wpl, DD, EE);
    }

    // 2) QKV = x @ W_attn + b_attn  [4096, 3072]
    {
        dim3 grid(3 * DD / 128, MM / 128);  // (24, 32)
        gemm_mma_kernel<<<grid, 256>>>(xh, xl, wah, wal, b_attn, qkv,
                                       MM, 3 * DD, GK);
    }

    // 3) flash attention -> y [4096, 1024]
    {
        dim3 grid(TT / 64, BB * HH);
        flash_attn_kernel<<<grid, 256, attn_smem>>>(qkv, y);
    }

    // 4) split y, then out = y @ W_proj + b_proj
    split_kernel<<<(MM * DD / 4 + 255) / 256, 256>>>(y, yh, yl, MM * DD / 4);
    {
        dim3 grid(EE / 128, MM / 128);  // (8, 32)
        gemm_mma_kernel<<<grid, 256>>>(yh, yl, wph, wpl, b_proj, out,
                                       MM, EE, GK);
    }
}

// round 7
// speedup vs baseline: 2.3030x; 1.6226x over previous
#include <cuda_runtime.h>
#include <cuda_bf16.h>
#include <cstdint>

// Problem constants
#define TT 2048
#define EE 1024
#define DD 1024
#define HH 16
#define HDIM 64
#define BB 2
#define MM (BB * TT)   // 4096
#define GK 1024        // K of both GEMMs

// ---------------------------------------------------------------------------
// Scratch (no runtime allocation allowed)
// ---------------------------------------------------------------------------
__device__ float g_qkv[(size_t)MM * 3 * DD];          // [4096, 3072] fp32
__device__ __nv_bfloat16 g_xh[(size_t)MM * EE];
__device__ __nv_bfloat16 g_xl[(size_t)MM * EE];
__device__ __nv_bfloat16 g_wah[(size_t)3 * DD * EE];  // W_attn^T [3072,1024]
__device__ __nv_bfloat16 g_wal[(size_t)3 * DD * EE];
__device__ __nv_bfloat16 g_wph[(size_t)EE * DD];      // W_proj^T [1024,1024]
__device__ __nv_bfloat16 g_wpl[(size_t)EE * DD];
__device__ __nv_bfloat16 g_yh[(size_t)MM * DD];       // attention out hi
__device__ __nv_bfloat16 g_yl[(size_t)MM * DD];       // attention out lo

// ---------------------------------------------------------------------------
// Warp-MMA helpers (base-target PTX: ldmatrix sm_75+, bf16 mma sm_80+)
// ---------------------------------------------------------------------------
__device__ __forceinline__ uint32_t smem_u32(const void* p) {
    uint32_t a;
    asm("{ .reg .u64 t; cvta.to.shared.u64 t, %1; cvt.u32.u64 %0, t; }"
        : "=r"(a) : "l"(p));
    return a;
}

#define LDSM_X4(R, addr) \
    asm volatile("ldmatrix.sync.aligned.m8n8.x4.shared.b16 {%0,%1,%2,%3}, [%4];" \
        : "=r"((R)[0]), "=r"((R)[1]), "=r"((R)[2]), "=r"((R)[3]) : "r"(addr))

#define MMA_BF16(D, A, B) \
    asm volatile("mma.sync.aligned.m16n8k16.row.col.f32.bf16.bf16.f32 " \
        "{%0,%1,%2,%3},{%4,%5,%6,%7},{%8,%9},{%0,%1,%2,%3};" \
        : "+f"((D)[0]), "+f"((D)[1]), "+f"((D)[2]), "+f"((D)[3]) \
        : "r"((A)[0]), "r"((A)[1]), "r"((A)[2]), "r"((A)[3]), \
          "r"((B)[0]), "r"((B)[1]))

__device__ __forceinline__ void split_bf16(float v, __nv_bfloat16& h, __nv_bfloat16& l) {
    h = __float2bfloat16(v);
    l = __float2bfloat16(v - __bfloat162float(h));
}
__device__ __forceinline__ uint32_t pack2(__nv_bfloat16 a, __nv_bfloat16 b) {
    __nv_bfloat162 t(a, b);
    return *(uint32_t*)&t;
}

// ---------------------------------------------------------------------------
// Split/convert kernels
// ---------------------------------------------------------------------------
__global__ void split_kernel(const float* __restrict__ in,
                             __nv_bfloat16* __restrict__ hi,
                             __nv_bfloat16* __restrict__ lo, int n4)
{
    int i = blockIdx.x * blockDim.x + threadIdx.x;
    if (i >= n4) return;
    float4 v = ((const float4*)in)[i];
    __nv_bfloat16 h0, h1, h2, h3, l0, l1, l2, l3;
    split_bf16(v.x, h0, l0); split_bf16(v.y, h1, l1);
    split_bf16(v.z, h2, l2); split_bf16(v.w, h3, l3);
    ((__nv_bfloat162*)hi)[2*i]   = __nv_bfloat162(h0, h1);
    ((__nv_bfloat162*)hi)[2*i+1] = __nv_bfloat162(h2, h3);
    ((__nv_bfloat162*)lo)[2*i]   = __nv_bfloat162(l0, l1);
    ((__nv_bfloat162*)lo)[2*i+1] = __nv_bfloat162(l2, l3);
}

// W [K,N] fp32 -> T [N,K] bf16 hi/lo
__global__ void transpose_split_kernel(const float* __restrict__ W,
                                       __nv_bfloat16* __restrict__ Th,
                                       __nv_bfloat16* __restrict__ Tl,
                                       int K, int N)
{
    __shared__ float tile[32][33];
    int kb = blockIdx.y * 32, nb = blockIdx.x * 32;
    int x = threadIdx.x, y0 = threadIdx.y;  // 32 x 8
    #pragma unroll
    for (int dy = 0; dy < 32; dy += 8)
        tile[y0 + dy][x] = W[(size_t)(kb + y0 + dy) * N + nb + x];
    __syncthreads();
    #pragma unroll
    for (int dy = 0; dy < 32; dy += 8) {
        float v = tile[x][y0 + dy];
        __nv_bfloat16 h, l;
        split_bf16(v, h, l);
        size_t o = (size_t)(nb + y0 + dy) * K + kb + x;
        Th[o] = h;
        Tl[o] = l;
    }
}

// ---------------------------------------------------------------------------
// mma.sync split-bf16 GEMM (unchanged from R6, proven): C = A @ Bt^T + bias
// ---------------------------------------------------------------------------
#define GS 40

__global__ __launch_bounds__(256) void gemm_mma_kernel(
    const __nv_bfloat16* __restrict__ Ah, const __nv_bfloat16* __restrict__ Al,
    const __nv_bfloat16* __restrict__ Bh, const __nv_bfloat16* __restrict__ Bl,
    const float* __restrict__ bias, float* __restrict__ C,
    int M, int N, int K)
{
    __shared__ __nv_bfloat16 sA[2][128][GS];
    __shared__ __nv_bfloat16 sB[2][128][GS];

    const int tid = threadIdx.x;
    const int lane = tid & 31;
    const int wid = tid >> 5;
    const int wm = wid & 3;
    const int wn = wid >> 2;
    const int m0 = blockIdx.y * 128;
    const int n0 = blockIdx.x * 128;

    const int lrow = tid >> 1;
    const int lseg = (tid & 1) * 16;

    float acc[2][8][4];
    #pragma unroll
    for (int i = 0; i < 2; i++)
        #pragma unroll
        for (int j = 0; j < 8; j++)
            #pragma unroll
            for (int r = 0; r < 4; r++) acc[i][j][r] = 0.f;

    const uint32_t sA0 = smem_u32(&sA[0][0][0]);
    const uint32_t sA1 = smem_u32(&sA[1][0][0]);
    const uint32_t sB0 = smem_u32(&sB[0][0][0]);
    const uint32_t sB1 = smem_u32(&sB[1][0][0]);

    uint4 pre[8];
    {
        size_t ra = (size_t)(m0 + lrow) * K + lseg;
        size_t rb = (size_t)(n0 + lrow) * K + lseg;
        pre[0] = *(const uint4*)&Ah[ra];
        pre[1] = *(const uint4*)&Ah[ra + 8];
        pre[2] = *(const uint4*)&Al[ra];
        pre[3] = *(const uint4*)&Al[ra + 8];
        pre[4] = *(const uint4*)&Bh[rb];
        pre[5] = *(const uint4*)&Bh[rb + 8];
        pre[6] = *(const uint4*)&Bl[rb];
        pre[7] = *(const uint4*)&Bl[rb + 8];
    }

    const int NC = K >> 5;
    for (int ch = 0; ch < NC; ch++) {
        *(uint4*)&sA[0][lrow][lseg]     = pre[0];
        *(uint4*)&sA[0][lrow][lseg + 8] = pre[1];
        *(uint4*)&sA[1][lrow][lseg]     = pre[2];
        *(uint4*)&sA[1][lrow][lseg + 8] = pre[3];
        *(uint4*)&sB[0][lrow][lseg]     = pre[4];
        *(uint4*)&sB[0][lrow][lseg + 8] = pre[5];
        *(uint4*)&sB[1][lrow][lseg]     = pre[6];
        *(uint4*)&sB[1][lrow][lseg + 8] = pre[7];
        __syncthreads();

        if (ch + 1 < NC) {
            int k0 = (ch + 1) * 32;
            size_t ra = (size_t)(m0 + lrow) * K + k0 + lseg;
            size_t rb = (size_t)(n0 + lrow) * K + k0 + lseg;
            pre[0] = *(const uint4*)&Ah[ra];
            pre[1] = *(const uint4*)&Ah[ra + 8];
            pre[2] = *(const uint4*)&Al[ra];
            pre[3] = *(const uint4*)&Al[ra + 8];
            pre[4] = *(const uint4*)&Bh[rb];
            pre[5] = *(const uint4*)&Bh[rb + 8];
            pre[6] = *(const uint4*)&Bl[rb];
            pre[7] = *(const uint4*)&Bl[rb + 8];
        }

        #pragma unroll
        for (int ks = 0; ks < 2; ks++) {
            uint32_t aA[2][2][4];
            {
                int r = lane & 15, kh = lane >> 4;
                #pragma unroll
                for (int mt = 0; mt < 2; mt++) {
                    uint32_t off =
                        (uint32_t)((wm * 32 + mt * 16 + r) * GS + ks * 16 + kh * 8) * 2;
                    LDSM_X4(aA[0][mt], sA0 + off);
                    LDSM_X4(aA[1][mt], sA1 + off);
                }
            }
            uint32_t bB[2][8][2];
            {
                int nr = ((lane >> 4) << 3) + (lane & 7);
                int kc = ks * 16 + (((lane >> 3) & 1) << 3);
                #pragma unroll
                for (int p = 0; p < 4; p++) {
                    uint32_t off =
                        (uint32_t)((wn * 64 + p * 16 + nr) * GS + kc) * 2;
                    uint32_t t[4];
                    LDSM_X4(t, sB0 + off);
                    bB[0][2 * p][0] = t[0]; bB[0][2 * p][1] = t[1];
                    bB[0][2 * p + 1][0] = t[2]; bB[0][2 * p + 1][1] = t[3];
                    LDSM_X4(t, sB1 + off);
                    bB[1][2 * p][0] = t[0]; bB[1][2 * p][1] = t[1];
                    bB[1][2 * p + 1][0] = t[2]; bB[1][2 * p + 1][1] = t[3];
                }
            }
            #pragma unroll
            for (int mt = 0; mt < 2; mt++)
                #pragma unroll
                for (int nt = 0; nt < 8; nt++) {
                    MMA_BF16(acc[mt][nt], aA[0][mt], bB[0][nt]);
                    MMA_BF16(acc[mt][nt], aA[0][mt], bB[1][nt]);
                    MMA_BF16(acc[mt][nt], aA[1][mt], bB[0][nt]);
                }
        }
        __syncthreads();
    }

    #pragma unroll
    for (int mt = 0; mt < 2; mt++) {
        int m = m0 + wm * 32 + mt * 16 + (lane >> 2);
        #pragma unroll
        for (int nt = 0; nt < 8; nt++) {
            int n = n0 + wn * 64 + nt * 8 + ((lane & 3) << 1);
            float b0 = bias[n], b1 = bias[n + 1];
            float2 lo = make_float2(acc[mt][nt][0] + b0, acc[mt][nt][1] + b1);
            float2 hi = make_float2(acc[mt][nt][2] + b0, acc[mt][nt][3] + b1);
            *(float2*)&C[(size_t)m * N + n] = lo;
            *(float2*)&C[(size_t)(m + 8) * N + n] = hi;
        }
    }
}

// ---------------------------------------------------------------------------
// Tensor-core flash attention (causal, split-bf16 both GEMMs).
// CTA: 128 q-rows of one (b,h); 8 warps x 16 rows (FA2 row ownership).
// Writes yh/yl bf16 splits directly (feeds proj GEMM; no fp32 y).
// ---------------------------------------------------------------------------
#define QS2 72    // sQ/sK row stride (bf16)
#define VS2 136   // sVt row stride (bf16)
// smem element offsets
#define OFF_QH 0
#define OFF_QL (128 * QS2)
#define OFF_KH (2 * 128 * QS2)
#define OFF_KL (3 * 128 * QS2)
#define OFF_VH (4 * 128 * QS2)
#define OFF_VL (4 * 128 * QS2 + 64 * VS2)
#define ATTN_SMEM ((4 * 128 * QS2 + 2 * 64 * VS2) * 2)   // bytes = 108544

__global__ __launch_bounds__(256) void flash_attn_mma_kernel(
    const float* __restrict__ qkv,
    __nv_bfloat16* __restrict__ yh, __nv_bfloat16* __restrict__ yl)
{
    extern __shared__ __nv_bfloat16 sm[];

    const int qt = 15 - blockIdx.x;        // big tiles first
    const int bh = blockIdx.y;
    const int b = bh >> 4, h = bh & 15;
    const int tid = threadIdx.x;
    const int lane = tid & 31;
    const int wid = tid >> 5;
    const int q0 = qt * 128;
    const size_t base = ((size_t)b * TT) * 3072 + (size_t)h * 64;

    const uint32_t sQh = smem_u32(sm + OFF_QH);
    const uint32_t sQl = smem_u32(sm + OFF_QL);
    const uint32_t sKh = smem_u32(sm + OFF_KH);
    const uint32_t sKl = smem_u32(sm + OFF_KL);
    const uint32_t sVh = smem_u32(sm + OFF_VH);
    const uint32_t sVl = smem_u32(sm + OFF_VL);

    // Load Q tile (scaled), split to smem.
    #pragma unroll
    for (int it = 0; it < 8; it++) {
        int idx = tid + 256 * it;          // 2048 float4
        int r = idx >> 4, c4 = (idx & 15) * 4;
        float4 v = *(const float4*)&qkv[base + (size_t)(q0 + r) * 3072 + c4];
        float f[4] = {v.x * 0.125f, v.y * 0.125f, v.z * 0.125f, v.w * 0.125f};
        #pragma unroll
        for (int j = 0; j < 4; j++) {
            __nv_bfloat16 hh, ll;
            split_bf16(f[j], hh, ll);
            sm[OFF_QH + r * QS2 + c4 + j] = hh;
            sm[OFF_QL + r * QS2 + c4 + j] = ll;
        }
    }
    __syncthreads();

    // Q fragments to registers (held across all k-tiles).
    uint32_t qA[2][4][4];
    {
        int r = lane & 15, kh = lane >> 4;
        #pragma unroll
        for (int ks = 0; ks < 4; ks++) {
            uint32_t off = (uint32_t)((wid * 16 + r) * QS2 + ks * 16 + kh * 8) * 2;
            LDSM_X4(qA[0][ks], sQh + off);
            LDSM_X4(qA[1][ks], sQl + off);
        }
    }

    float mS[2] = {-1e30f, -1e30f};
    float lS[2] = {0.f, 0.f};
    float oAcc[8][4];
    #pragma unroll
    for (int j = 0; j < 8; j++)
        #pragma unroll
        for (int r = 0; r < 4; r++) oAcc[j][r] = 0.f;

    const int nr = ((lane >> 4) << 3) + (lane & 7);
    const int kc8 = ((lane >> 3) & 1) << 3;

    for (int kt = 0; kt <= qt; kt++) {
        __syncthreads();   // previous tile's smem reads done
        // Load K tile (row = kcol, col = d) and V tile transposed (row = d).
        #pragma unroll
        for (int it = 0; it < 8; it++) {
            int idx = tid + 256 * it;
            int r = idx >> 4, c4 = (idx & 15) * 4;
            float4 v = *(const float4*)&qkv[base + 1024 +
                                            (size_t)(kt * 128 + r) * 3072 + c4];
            float f[4] = {v.x, v.y, v.z, v.w};
            #pragma unroll
            for (int j = 0; j < 4; j++) {
                __nv_bfloat16 hh, ll;
                split_bf16(f[j], hh, ll);
                sm[OFF_KH + r * QS2 + c4 + j] = hh;
                sm[OFF_KL + r * QS2 + c4 + j] = ll;
            }
            float4 w = *(const float4*)&qkv[base + 2048 +
                                            (size_t)(kt * 128 + r) * 3072 + c4];
            float g[4] = {w.x, w.y, w.z, w.w};
            #pragma unroll
            for (int j = 0; j < 4; j++) {
                __nv_bfloat16 hh, ll;
                split_bf16(g[j], hh, ll);
                sm[OFF_VH + (c4 + j) * VS2 + r] = hh;
                sm[OFF_VL + (c4 + j) * VS2 + r] = ll;
            }
        }
        __syncthreads();

        // S = Q @ K^T  (16 x 128 per warp)
        float sAcc[16][4];
        #pragma unroll
        for (int j = 0; j < 16; j++)
            #pragma unroll
            for (int r = 0; r < 4; r++) sAcc[j][r] = 0.f;

        #pragma unroll
        for (int ks = 0; ks < 4; ks++) {
            #pragma unroll
            for (int p = 0; p < 8; p++) {
                uint32_t off = (uint32_t)((p * 16 + nr) * QS2 + ks * 16 + kc8) * 2;
                uint32_t kbH[4], kbL[4];
                LDSM_X4(kbH, sKh + off);
                LDSM_X4(kbL, sKl + off);
                MMA_BF16(sAcc[2 * p], qA[0][ks], &kbH[0]);
                MMA_BF16(sAcc[2 * p], qA[0][ks], &kbL[0]);
                MMA_BF16(sAcc[2 * p], qA[1][ks], &kbH[0]);
                MMA_BF16(sAcc[2 * p + 1], qA[0][ks], &kbH[2]);
                MMA_BF16(sAcc[2 * p + 1], qA[0][ks], &kbL[2]);
                MMA_BF16(sAcc[2 * p + 1], qA[1][ks], &kbH[2]);
            }
        }

        // Causal mask (diagonal tile only; q0 == kt*128 there).
        if (kt == qt) {
            int r0 = wid * 16 + (lane >> 2);
            #pragma unroll
            for (int j = 0; j < 16; j++) {
                int c0 = j * 8 + (lane & 3) * 2;
                if (c0 > r0)     sAcc[j][0] = -1e30f;
                if (c0 + 1 > r0) sAcc[j][1] = -1e30f;
                if (c0 > r0 + 8)     sAcc[j][2] = -1e30f;
                if (c0 + 1 > r0 + 8) sAcc[j][3] = -1e30f;
            }
        }

        // Online softmax (rows r0 and r0+8; 4-lane row groups).
        #pragma unroll
        for (int hf = 0; hf < 2; hf++) {
            float rm = -1e30f;
            #pragma unroll
            for (int j = 0; j < 16; j++)
                rm = fmaxf(rm, fmaxf(sAcc[j][2 * hf], sAcc[j][2 * hf + 1]));
            rm = fmaxf(rm, __shfl_xor_sync(0xffffffffu, rm, 1));
            rm = fmaxf(rm, __shfl_xor_sync(0xffffffffu, rm, 2));
            float nm = fmaxf(mS[hf], rm);
            float alpha = __expf(mS[hf] - nm);
            mS[hf] = nm;
            float sum = 0.f;
            #pragma unroll
            for (int j = 0; j < 16; j++) {
                float p0 = __expf(sAcc[j][2 * hf] - nm);
                float p1 = __expf(sAcc[j][2 * hf + 1] - nm);
                sAcc[j][2 * hf] = p0;
                sAcc[j][2 * hf + 1] = p1;
                sum += p0 + p1;
            }
            sum += __shfl_xor_sync(0xffffffffu, sum, 1);
            sum += __shfl_xor_sync(0xffffffffu, sum, 2);
            lS[hf] = lS[hf] * alpha + sum;
            #pragma unroll
            for (int j = 0; j < 8; j++) {
                oAcc[j][2 * hf] *= alpha;
                oAcc[j][2 * hf + 1] *= alpha;
            }
        }

        // Pack P into A-fragments (hi/lo), k-chunk t = S n-tiles 2t, 2t+1.
        uint32_t pH[8][4], pL[8][4];
        #pragma unroll
        for (int t = 0; t < 8; t++) {
            #pragma unroll
            for (int q = 0; q < 4; q++) {
                int nt = 2 * t + (q >> 1);
                int i0 = (q & 1) * 2;
                __nv_bfloat16 h0, l0, h1, l1;
                split_bf16(sAcc[nt][i0], h0, l0);
                split_bf16(sAcc[nt][i0 + 1], h1, l1);
                pH[t][q] = pack2(h0, h1);
                pL[t][q] = pack2(l0, l1);
            }
        }

        // O += P @ V  (16 x 64 per warp; V^T rows = d)
        #pragma unroll
        for (int t = 0; t < 8; t++) {
            #pragma unroll
            for (int p = 0; p < 4; p++) {
                uint32_t off = (uint32_t)((p * 16 + nr) * VS2 + t * 16 + kc8) * 2;
                uint32_t vbH[4], vbL[4];
                LDSM_X4(vbH, sVh + off);
                LDSM_X4(vbL, sVl + off);
                MMA_BF16(oAcc[2 * p], pH[t], &vbH[0]);
                MMA_BF16(oAcc[2 * p], pH[t], &vbL[0]);
                MMA_BF16(oAcc[2 * p], pL[t], &vbH[0]);
                MMA_BF16(oAcc[2 * p + 1], pH[t], &vbH[2]);
                MMA_BF16(oAcc[2 * p + 1], pH[t], &vbL[2]);
                MMA_BF16(oAcc[2 * p + 1], pL[t], &vbH[2]);
            }
        }
    }

    // Epilogue: normalize, split to bf16 hi/lo, store to yh/yl.
    {
        float inv0 = 1.0f / lS[0];
        float inv1 = 1.0f / lS[1];
        int r0 = q0 + wid * 16 + (lane >> 2);
        size_t row0 = (size_t)b * TT + r0;
        #pragma unroll
        for (int j = 0; j < 8; j++) {
            int col = h * 64 + j * 8 + (lane & 3) * 2;
            float y0 = oAcc[j][0] * inv0, y1 = oAcc[j][1] * inv0;
            float y2 = oAcc[j][2] * inv1, y3 = oAcc[j][3] * inv1;
            __nv_bfloat16 h0, l0, h1, l1, h2, l2, h3, l3;
            split_bf16(y0, h0, l0); split_bf16(y1, h1, l1);
            split_bf16(y2, h2, l2); split_bf16(y3, h3, l3);
            *(uint32_t*)&yh[row0 * 1024 + col] = pack2(h0, h1);
            *(uint32_t*)&yl[row0 * 1024 + col] = pack2(l0, l1);
            *(uint32_t*)&yh[(row0 + 8) * 1024 + col] = pack2(h2, h3);
            *(uint32_t*)&yl[(row0 + 8) * 1024 + col] = pack2(l2, l3);
        }
    }
}

// ---------------------------------------------------------------------------
extern "C" void kernel_launch(void* const* d_in, const int* in_sizes, int n_in,
                              void* d_out, int out_size)
{
    const float* x      = (const float*)d_in[0];
    const float* W_attn = (const float*)d_in[1];
    const float* b_attn = (const float*)d_in[2];
    const float* W_proj = (const float*)d_in[3];
    const float* b_proj = (const float*)d_in[4];
    float* out = (float*)d_out;

    float* qkv;
    __nv_bfloat16 *xh, *xl, *wah, *wal, *wph, *wpl, *yh, *yl;
    cudaGetSymbolAddress((void**)&qkv, g_qkv);
    cudaGetSymbolAddress((void**)&xh, g_xh);
    cudaGetSymbolAddress((void**)&xl, g_xl);
    cudaGetSymbolAddress((void**)&wah, g_wah);
    cudaGetSymbolAddress((void**)&wal, g_wal);
    cudaGetSymbolAddress((void**)&wph, g_wph);
    cudaGetSymbolAddress((void**)&wpl, g_wpl);
    cudaGetSymbolAddress((void**)&yh, g_yh);
    cudaGetSymbolAddress((void**)&yl, g_yl);

    static bool attr_set = false;
    if (!attr_set) {
        cudaFuncSetAttribute(flash_attn_mma_kernel,
                             cudaFuncAttributeMaxDynamicSharedMemorySize,
                             ATTN_SMEM);
        attr_set = true;
    }

    // 1) splits / transposes
    split_kernel<<<(MM * EE / 4 + 255) / 256, 256>>>(x, xh, xl, MM * EE / 4);
    {
        dim3 g(3 * DD / 32, EE / 32), b(32, 8);
        transpose_split_kernel<<<g, b>>>(W_attn, wah, wal, EE, 3 * DD);
    }
    {
        dim3 g(EE / 32, DD / 32), b(32, 8);
        transpose_split_kernel<<<g, b>>>(W_proj, wph, wpl, DD, EE);
    }

    // 2) QKV = x @ W_attn + b_attn  [4096, 3072]
    {
        dim3 grid(3 * DD / 128, MM / 128);  // (24, 32)
        gemm_mma_kernel<<<grid, 256>>>(xh, xl, wah, wal, b_attn, qkv,
                                       MM, 3 * DD, GK);
    }

    // 3) tensor-core flash attention -> yh/yl bf16 splits
    {
        dim3 grid(TT / 128, BB * HH);       // (16, 32)
        flash_attn_mma_kernel<<<grid, 256, ATTN_SMEM>>>(qkv, yh, yl);
    }

    // 4) out = y @ W_proj + b_proj
    {
        dim3 grid(EE / 128, MM / 128);      // (8, 32)
        gemm_mma_kernel<<<grid, 256>>>(yh, yl, wph, wpl, b_proj, out,
                                       MM, EE, GK);
    }
}